// round 1
// baseline (speedup 1.0000x reference)
#include <cuda_runtime.h>
#include <cuda_bf16.h>
#include <cstdint>

#define VOCAB 12288
#define EMB   128
#define TILE  128
#define SSTR  136   // smem row stride in bf16 elems (128 + 8 pad -> conflict-free frag loads)

// Preconverted bf16 embeddings (allocation-free scratch).
__device__ __nv_bfloat16 g_ctx[VOCAB * EMB];
__device__ __nv_bfloat16 g_tgt[VOCAB * EMB];

// ---------------------------------------------------------------------------
// fp32 -> bf16 conversion of both embedding tables. 8 elems / thread.
// ---------------------------------------------------------------------------
__global__ void convert_kernel(const float* __restrict__ tgt,
                               const float* __restrict__ ctx) {
    int t = blockIdx.x * blockDim.x + threadIdx.x;   // 0 .. VOCAB*EMB/8 - 1
    int base = t * 8;
    if (base >= VOCAB * EMB) return;

    float4 a0 = *(const float4*)(tgt + base);
    float4 a1 = *(const float4*)(tgt + base + 4);
    float4 b0 = *(const float4*)(ctx + base);
    float4 b1 = *(const float4*)(ctx + base + 4);

    __nv_bfloat162 ta[4], ca[4];
    ta[0] = __floats2bfloat162_rn(a0.x, a0.y);
    ta[1] = __floats2bfloat162_rn(a0.z, a0.w);
    ta[2] = __floats2bfloat162_rn(a1.x, a1.y);
    ta[3] = __floats2bfloat162_rn(a1.z, a1.w);
    ca[0] = __floats2bfloat162_rn(b0.x, b0.y);
    ca[1] = __floats2bfloat162_rn(b0.z, b0.w);
    ca[2] = __floats2bfloat162_rn(b1.x, b1.y);
    ca[3] = __floats2bfloat162_rn(b1.z, b1.w);

    *(uint4*)(g_tgt + base) = *(const uint4*)ta;
    *(uint4*)(g_ctx + base) = *(const uint4*)ca;
}

__global__ void zero_kernel(float* out) { out[0] = 0.0f; }

// ---------------------------------------------------------------------------
// mma.sync m16n8k16 bf16 -> f32
// ---------------------------------------------------------------------------
__device__ __forceinline__ void mma_bf16(float c[4], const uint32_t a[4],
                                         const uint32_t b[2]) {
    asm volatile(
        "mma.sync.aligned.m16n8k16.row.col.f32.bf16.bf16.f32 "
        "{%0,%1,%2,%3}, {%4,%5,%6,%7}, {%8,%9}, {%0,%1,%2,%3};\n"
        : "+f"(c[0]), "+f"(c[1]), "+f"(c[2]), "+f"(c[3])
        : "r"(a[0]), "r"(a[1]), "r"(a[2]), "r"(a[3]), "r"(b[0]), "r"(b[1]));
}

// ---------------------------------------------------------------------------
// Fused kernel: one 128x128 tile of dots per block, epilogue streams X,
// computes weight * diff^2 and reduces.
// Block: 256 threads = 8 warps laid out 4 (M) x 2 (N); warp tile 32 x 64.
// ---------------------------------------------------------------------------
extern __shared__ __nv_bfloat16 smem[];   // A tile then B tile, SSTR stride

__global__ void __launch_bounds__(256, 2)
glove_kernel(const float* __restrict__ X,
             const float* __restrict__ tb,   // target_bias   [V]
             const float* __restrict__ cb,   // context_bias  [V]
             float* __restrict__ out) {
    const int bi = blockIdx.y;   // context (row) tile
    const int bj = blockIdx.x;   // target  (col) tile

    __nv_bfloat16* As = smem;                   // context tile: 128 x 128 (stride SSTR)
    __nv_bfloat16* Bs = smem + TILE * SSTR;     // target  tile

    const int tid  = threadIdx.x;
    const int warp = tid >> 5;
    const int lane = tid & 31;
    const int wm   = warp >> 1;          // 0..3 -> row offset wm*32
    const int wn   = warp & 1;           // 0..1 -> col offset wn*64
    const int g    = lane >> 2;          // group id 0..7
    const int tig  = lane & 3;           // thread-in-group 0..3

    // ---- stage tiles GMEM(bf16) -> SMEM -------------------------------------
    {
        const __nv_bfloat16* gA = g_ctx + (size_t)(bi * TILE) * EMB;
        const __nv_bfloat16* gB = g_tgt + (size_t)(bj * TILE) * EMB;
        #pragma unroll
        for (int it = 0; it < 8; it++) {
            int linear = tid + it * 256;      // 0 .. 2047
            int row = linear >> 4;            // 16 uint4 per row
            int c16 = linear & 15;
            *(uint4*)(As + row * SSTR + c16 * 8) =
                *(const uint4*)(gA + row * EMB + c16 * 8);
            *(uint4*)(Bs + row * SSTR + c16 * 8) =
                *(const uint4*)(gB + row * EMB + c16 * 8);
        }
    }
    __syncthreads();

    // ---- GEMM: acc[mt][nt][4] ----------------------------------------------
    float acc[2][8][4];
    #pragma unroll
    for (int mt = 0; mt < 2; mt++)
        #pragma unroll
        for (int nt = 0; nt < 8; nt++)
            #pragma unroll
            for (int r = 0; r < 4; r++) acc[mt][nt][r] = 0.0f;

    const int m0 = wm * 32;
    const int n0 = wn * 64;

    #pragma unroll
    for (int ko = 0; ko < EMB; ko += 16) {
        uint32_t afr[2][4];
        #pragma unroll
        for (int mt = 0; mt < 2; mt++) {
            const __nv_bfloat16* ap = As + (m0 + mt * 16 + g) * SSTR + ko + 2 * tig;
            afr[mt][0] = *(const uint32_t*)(ap);
            afr[mt][1] = *(const uint32_t*)(ap + 8 * SSTR);
            afr[mt][2] = *(const uint32_t*)(ap + 8);
            afr[mt][3] = *(const uint32_t*)(ap + 8 * SSTR + 8);
        }
        uint32_t bfr[8][2];
        #pragma unroll
        for (int nt = 0; nt < 8; nt++) {
            const __nv_bfloat16* bp = Bs + (n0 + nt * 8 + g) * SSTR + ko + 2 * tig;
            bfr[nt][0] = *(const uint32_t*)(bp);
            bfr[nt][1] = *(const uint32_t*)(bp + 8);
        }
        #pragma unroll
        for (int mt = 0; mt < 2; mt++)
            #pragma unroll
            for (int nt = 0; nt < 8; nt++)
                mma_bf16(acc[mt][nt], afr[mt], bfr[nt]);
    }

    // ---- fused epilogue ------------------------------------------------------
    // c0,c1 -> row g,   cols 2*tig, 2*tig+1
    // c2,c3 -> row g+8, cols 2*tig, 2*tig+1
    float tsum = 0.0f;
    const int jwarp = bj * TILE + n0;             // warp's global col base

    #pragma unroll
    for (int mt = 0; mt < 2; mt++) {
        #pragma unroll
        for (int h = 0; h < 2; h++) {
            const int i  = bi * TILE + m0 + mt * 16 + g + h * 8;
            const float cbi = cb[i];
            const float* xrow = X + (size_t)i * VOCAB + jwarp;
            #pragma unroll
            for (int nt = 0; nt < 8; nt++) {
                const int joff = nt * 8 + 2 * tig;
                float2 xx  = *(const float2*)(xrow + joff);
                float2 tb2 = *(const float2*)(tb + jwarp + joff);

                {
                    float x = xx.x;
                    float d = acc[mt][nt][h * 2 + 0] + tb2.x + cbi - __logf(1.0f + x);
                    float w = fminf(__powf(x * 0.01f, 0.75f), 1.0f);
                    tsum = fmaf(w * d, d, tsum);
                }
                {
                    float x = xx.y;
                    float d = acc[mt][nt][h * 2 + 1] + tb2.y + cbi - __logf(1.0f + x);
                    float w = fminf(__powf(x * 0.01f, 0.75f), 1.0f);
                    tsum = fmaf(w * d, d, tsum);
                }
            }
        }
    }

    // ---- reduction -----------------------------------------------------------
    #pragma unroll
    for (int off = 16; off > 0; off >>= 1)
        tsum += __shfl_xor_sync(0xFFFFFFFFu, tsum, off);

    __shared__ float red[8];
    if (lane == 0) red[warp] = tsum;
    __syncthreads();
    if (warp == 0) {
        float v = (lane < 8) ? red[lane] : 0.0f;
        #pragma unroll
        for (int off = 4; off > 0; off >>= 1)
            v += __shfl_xor_sync(0xFFFFFFFFu, v, off);
        if (lane == 0) atomicAdd(out, v);
    }
}

// ---------------------------------------------------------------------------
extern "C" void kernel_launch(void* const* d_in, const int* in_sizes, int n_in,
                              void* d_out, int out_size) {
    const float* X   = (const float*)d_in[0];   // matriz_coocurrencias [V,V]
    const float* te  = (const float*)d_in[1];   // target_emb  [V,E]
    const float* ce  = (const float*)d_in[2];   // context_emb [V,E]
    const float* tbp = (const float*)d_in[3];   // target_bias [V,1]
    const float* cbp = (const float*)d_in[4];   // context_bias[V,1]
    float* out = (float*)d_out;

    static bool attr_set = false;
    const int smem_bytes = 2 * TILE * SSTR * (int)sizeof(__nv_bfloat16); // 69632
    if (!attr_set) {
        cudaFuncSetAttribute(glove_kernel,
                             cudaFuncAttributeMaxDynamicSharedMemorySize,
                             smem_bytes);
        attr_set = true;
    }

    const int conv_threads = VOCAB * EMB / 8;
    convert_kernel<<<(conv_threads + 255) / 256, 256>>>(te, ce);
    zero_kernel<<<1, 1>>>(out);

    dim3 grid(VOCAB / TILE, VOCAB / TILE);   // 96 x 96
    glove_kernel<<<grid, 256, smem_bytes>>>(X, tbp, cbp, out);
    (void)in_sizes; (void)n_in; (void)out_size;
}